// round 2
// baseline (speedup 1.0000x reference)
#include <cuda_runtime.h>
#include <cstdint>

// Problem constants (fixed shapes for this problem)
#define BATCH 2048
#define DIM   512
#define NOUT  16384
#define SIDE  128

// Scratch (no cudaMalloc allowed)
__device__ float g_w2[NOUT];
__device__ float g_x2[BATCH];
__device__ unsigned long long g_argmin[BATCH];

// ---------------------------------------------------------------------------
// Kernel 1: w2[n] = sum_d W[d][n]^2   (W is D x N row-major)
// ---------------------------------------------------------------------------
__global__ void prep_w2_kernel(const float* __restrict__ w) {
    int n = blockIdx.x * blockDim.x + threadIdx.x;
    if (n >= NOUT) return;
    float s0 = 0.f, s1 = 0.f, s2 = 0.f, s3 = 0.f;
#pragma unroll 4
    for (int d = 0; d < DIM; d += 4) {
        float a = w[(size_t)(d + 0) * NOUT + n];
        float b = w[(size_t)(d + 1) * NOUT + n];
        float c = w[(size_t)(d + 2) * NOUT + n];
        float e = w[(size_t)(d + 3) * NOUT + n];
        s0 = fmaf(a, a, s0);
        s1 = fmaf(b, b, s1);
        s2 = fmaf(c, c, s2);
        s3 = fmaf(e, e, s3);
    }
    g_w2[n] = (s0 + s1) + (s2 + s3);
}

// ---------------------------------------------------------------------------
// Kernel 2: x2[b] = sum_d x[b][d]^2  + init g_argmin. One warp per row.
// ---------------------------------------------------------------------------
__global__ void prep_x2_kernel(const float* __restrict__ x) {
    int warp = (blockIdx.x * blockDim.x + threadIdx.x) >> 5;
    int lane = threadIdx.x & 31;
    if (warp >= BATCH) return;
    const float4* row = (const float4*)(x + (size_t)warp * DIM);
    float s = 0.f;
#pragma unroll
    for (int i = 0; i < 4; i++) {
        float4 v = row[lane + i * 32];
        s = fmaf(v.x, v.x, s);
        s = fmaf(v.y, v.y, s);
        s = fmaf(v.z, v.z, s);
        s = fmaf(v.w, v.w, s);
    }
#pragma unroll
    for (int off = 16; off > 0; off >>= 1)
        s += __shfl_down_sync(0xFFFFFFFFu, s, off);
    if (lane == 0) {
        g_x2[warp] = s;
        g_argmin[warp] = ~0ULL;
    }
}

// ---------------------------------------------------------------------------
// Kernel 3: fused GEMM + distance epilogue + per-row argmin.
//   norms2[b][n] = max(x2[b] + w2[n] - 2 * dot(x[b], W[:,n]), 0)
// Tile: BM=128, BN=128, BK=16, 256 threads, 8x8 per thread.
// ---------------------------------------------------------------------------
#define BM 128
#define BN 128
#define BK 16
#define TM 8
#define TN 8

__global__ __launch_bounds__(256, 2)
void gemm_dist_kernel(const float* __restrict__ x, const float* __restrict__ w,
                      float* __restrict__ out) {
    __shared__ float As[BK][BM + 4];   // transposed A tile
    __shared__ float Bs[BK][BN];

    const int tid = threadIdx.x;
    const int tx = tid & 15;           // 0..15 -> column group
    const int ty = tid >> 4;           // 0..15 -> row group
    const int rowBase = blockIdx.y * BM;
    const int colBase = blockIdx.x * BN;

    float acc[TM][TN];
#pragma unroll
    for (int i = 0; i < TM; i++)
#pragma unroll
        for (int j = 0; j < TN; j++) acc[i][j] = 0.f;

    for (int k0 = 0; k0 < DIM; k0 += BK) {
        // Load A tile (128 rows x 16 k), 512 float4s, 2 per thread, transpose.
#pragma unroll
        for (int i = 0; i < 2; i++) {
            int li = tid + i * 256;         // 0..511 (float4 units)
            int r  = li >> 2;               // 0..127
            int kq = (li & 3) << 2;         // 0,4,8,12
            float4 v = *(const float4*)(x + (size_t)(rowBase + r) * DIM + k0 + kq);
            As[kq + 0][r] = v.x;
            As[kq + 1][r] = v.y;
            As[kq + 2][r] = v.z;
            As[kq + 3][r] = v.w;
        }
        // Load B tile (16 k x 128 cols), 512 float4s, 2 per thread.
#pragma unroll
        for (int i = 0; i < 2; i++) {
            int li = tid + i * 256;         // 0..511
            int kr = li >> 5;               // 0..15
            int c  = (li & 31) << 2;        // 0..124
            *(float4*)&Bs[kr][c] =
                *(const float4*)(w + (size_t)(k0 + kr) * NOUT + colBase + c);
        }
        __syncthreads();

#pragma unroll
        for (int kk = 0; kk < BK; kk++) {
            float a[TM], b[TN];
#pragma unroll
            for (int i = 0; i < TM; i++) a[i] = As[kk][ty * TM + i];
#pragma unroll
            for (int j = 0; j < TN; j++) b[j] = Bs[kk][tx * TN + j];
#pragma unroll
            for (int i = 0; i < TM; i++)
#pragma unroll
                for (int j = 0; j < TN; j++)
                    acc[i][j] = fmaf(a[i], b[j], acc[i][j]);
        }
        __syncthreads();
    }

    // Epilogue: distances + store + per-row argmin tracking.
    float w2r[TN];
#pragma unroll
    for (int j = 0; j < TN; j++) w2r[j] = g_w2[colBase + tx * TN + j];

    unsigned long long pk[TM];
#pragma unroll
    for (int i = 0; i < TM; i++) {
        int row = rowBase + ty * TM + i;
        float xs = g_x2[row];
        float v[TN];
        unsigned long long best = ~0ULL;
#pragma unroll
        for (int j = 0; j < TN; j++) {
            int col = colBase + tx * TN + j;
            float d = fmaxf(fmaf(-2.f, acc[i][j], xs + w2r[j]), 0.f);
            v[j] = d;
            unsigned long long p =
                ((unsigned long long)__float_as_uint(d) << 32) | (unsigned)col;
            best = (p < best) ? p : best;
        }
        pk[i] = best;
        float* op = out + (size_t)row * NOUT + colBase + tx * TN;
        *(float4*)op       = make_float4(v[0], v[1], v[2], v[3]);
        *(float4*)(op + 4) = make_float4(v[4], v[5], v[6], v[7]);
    }

    // Reduce argmin across the 16 column-group threads of each row.
    __shared__ unsigned long long red[16][17];
#pragma unroll
    for (int i = 0; i < TM; i++) {
        red[ty][tx] = pk[i];
        __syncthreads();
        if (tx == 0) {
            unsigned long long m = red[ty][0];
#pragma unroll
            for (int t = 1; t < 16; t++) {
                unsigned long long q = red[ty][t];
                m = (q < m) ? q : m;
            }
            atomicMin(&g_argmin[rowBase + ty * TM + i], m);
        }
        __syncthreads();
    }
}

// ---------------------------------------------------------------------------
// Kernel 4: phi epilogue. phi is separable over (row,col) of the 2D grid:
//   sum_n exp(-d2/2s^2) = (sum_r er) * (sum_c ec)
// out[b][n] = norms2[b][n] * er[n>>7] * ec[n&127] / denom
// One block per batch row.
// ---------------------------------------------------------------------------
__global__ __launch_bounds__(256)
void phi_kernel(float* __restrict__ out, const float* __restrict__ std_ptr) {
    __shared__ float er[SIDE], ec[SIDE];
    __shared__ float s_inv;
    const int b = blockIdx.x;
    const int tid = threadIdx.x;

    unsigned long long packed = g_argmin[b];
    int idx = (int)(packed & 0xFFFFFFFFu);
    int cr = idx >> 7;       // idx / SIDE
    int cc = idx & 127;      // idx % SIDE

    float stdv = *std_ptr;
    float coef = 0.5f / (stdv * stdv);

    if (tid < SIDE) {
        float d = (float)(tid - cr);
        er[tid] = expf(-d * d * coef);
    } else if (tid < 2 * SIDE) {
        int t = tid - SIDE;
        float d = (float)(t - cc);
        ec[t] = expf(-d * d * coef);
    }
    __syncthreads();

    if (tid == 0) {
        float sr = 0.f, sc = 0.f;
        for (int t = 0; t < SIDE; t++) { sr += er[t]; sc += ec[t]; }
        s_inv = 1.0f / (sr * sc);
    }
    __syncthreads();

    float inv = s_inv;
    float* base = out + (size_t)b * NOUT;
#pragma unroll 4
    for (int n = tid; n < NOUT; n += 256) {
        base[n] = base[n] * (er[n >> 7] * ec[n & 127] * inv);
    }
}

// ---------------------------------------------------------------------------
extern "C" void kernel_launch(void* const* d_in, const int* in_sizes, int n_in,
                              void* d_out, int out_size) {
    const float* x   = (const float*)d_in[0];   // (2048, 512)
    const float* wts = (const float*)d_in[1];   // (512, 16384)
    const float* std = (const float*)d_in[2];   // scalar
    float* out = (float*)d_out;                 // (2048, 16384)

    prep_w2_kernel<<<NOUT / 256, 256>>>(wts);
    prep_x2_kernel<<<BATCH / 8, 256>>>(x);      // 8 warps/block, 1 warp/row

    dim3 grid(NOUT / BN, BATCH / BM);           // (128, 16)
    gemm_dist_kernel<<<grid, 256>>>(x, wts, out);

    phi_kernel<<<BATCH, 256>>>(out, std);
}

// round 11
// speedup vs baseline: 2.2325x; 2.2325x over previous
#include <cuda_runtime.h>
#include <cstdint>

#define BATCH 2048
#define DIM   512
#define NOUT  16384
#define SIDE  128

// ---------------- device scratch (no cudaMalloc allowed) ----------------
__device__ float g_w2[NOUT];
__device__ float g_x2[BATCH];
__device__ unsigned long long g_argmin[BATCH];

__device__ __forceinline__ uint32_t smem_u32(const void* p) {
    uint32_t a;
    asm("{ .reg .u64 t; cvta.to.shared.u64 t, %1; cvt.u32.u64 %0, t; }"
        : "=r"(a) : "l"(p));
    return a;
}

// ---------------------------------------------------------------------------
// Kernel: w2[n] = sum_d W[d][n]^2 (exact fp32)
// ---------------------------------------------------------------------------
__global__ void prep_w2_kernel(const float* __restrict__ w) {
    int n = blockIdx.x * blockDim.x + threadIdx.x;
    float s0 = 0.f, s1 = 0.f, s2 = 0.f, s3 = 0.f;
#pragma unroll 4
    for (int d = 0; d < DIM; d += 4) {
        float a = w[(size_t)(d + 0) * NOUT + n];
        float b = w[(size_t)(d + 1) * NOUT + n];
        float c = w[(size_t)(d + 2) * NOUT + n];
        float e = w[(size_t)(d + 3) * NOUT + n];
        s0 = fmaf(a, a, s0); s1 = fmaf(b, b, s1);
        s2 = fmaf(c, c, s2); s3 = fmaf(e, e, s3);
    }
    g_w2[n] = (s0 + s1) + (s2 + s3);
}

// ---------------------------------------------------------------------------
// Kernel: x2[b] = sum_d x[b][d]^2 (exact) + init argmin. One warp per row.
// ---------------------------------------------------------------------------
__global__ void prep_x2_kernel(const float* __restrict__ x) {
    int warp = (blockIdx.x * blockDim.x + threadIdx.x) >> 5;
    int lane = threadIdx.x & 31;
    if (warp >= BATCH) return;
    const float4* row = (const float4*)(x + (size_t)warp * DIM);
    float s = 0.f;
#pragma unroll
    for (int i = 0; i < 4; i++) {
        float4 v = row[lane + i * 32];
        s = fmaf(v.x, v.x, s); s = fmaf(v.y, v.y, s);
        s = fmaf(v.z, v.z, s); s = fmaf(v.w, v.w, s);
    }
#pragma unroll
    for (int off = 16; off > 0; off >>= 1) s += __shfl_down_sync(0xFFFFFFFFu, s, off);
    if (lane == 0) { g_x2[warp] = s; g_argmin[warp] = ~0ULL; }
}

// ---------------------------------------------------------------------------
// tf32 mma.sync GEMM (portable sm_80+ path; tcgen05 unavailable on the
// harness's base sm_103 ptx target).
// Tile: 128(M) x 128(N), BK=32, 8 warps in 2x4 grid, warp tile 64x32.
// Double-buffered cp.async. Epilogue: dist = max(x2+w2-2dot,0), per-row
// argmin (quad shfl -> smem atomic -> global atomic), direct float2 stores.
// ---------------------------------------------------------------------------
#define BM 128
#define BN 128
#define KT 32
#define NCHUNK (DIM / KT)              // 16
#define AS_STRIDE 36                   // floats; banks 4g+t conflict-free
#define BS_STRIDE 136                  // floats; banks 8t+g conflict-free
#define AS_FLOATS (BM * AS_STRIDE)     // 4608
#define BS_FLOATS (KT * BS_STRIDE)     // 4352
#define STAGE_FLOATS (AS_FLOATS + BS_FLOATS)   // 8960
#define GEMM_SMEM (2 * STAGE_FLOATS * 4 + 1024) // 72704 bytes

#define CP_ASYNC16(dst, src) \
    asm volatile("cp.async.cg.shared.global [%0], [%1], 16;" :: "r"(dst), "l"(src))
#define CP_COMMIT() asm volatile("cp.async.commit_group;" ::: "memory")
#define CP_WAIT(n)  asm volatile("cp.async.wait_group %0;" :: "n"(n) : "memory")

#define MMA_TF32(c0, c1, c2, c3, a0, a1, a2, a3, b0, b1) \
    asm volatile( \
        "mma.sync.aligned.m16n8k8.row.col.f32.tf32.tf32.f32 " \
        "{%0,%1,%2,%3}, {%4,%5,%6,%7}, {%8,%9}, {%0,%1,%2,%3};" \
        : "+f"(c0), "+f"(c1), "+f"(c2), "+f"(c3) \
        : "r"(a0), "r"(a1), "r"(a2), "r"(a3), "r"(b0), "r"(b1))

__global__ __launch_bounds__(256, 2)
void gemm_mma_kernel(const float* __restrict__ x, const float* __restrict__ w,
                     float* __restrict__ out) {
    extern __shared__ float sm[];
    unsigned long long* sred = (unsigned long long*)(sm + 2 * STAGE_FLOATS);

    const int tid = threadIdx.x;
    const int lane = tid & 31;
    const int wrp = tid >> 5;
    const int wm = wrp >> 2;           // 0..1  (M half)
    const int wn = wrp & 3;            // 0..3  (N quarter)
    const int g = lane >> 2;           // 0..7
    const int t = lane & 3;            // 0..3
    const int rowBase = blockIdx.y * BM;
    const int colBase = blockIdx.x * BN;

    if (tid < BM) sred[tid] = ~0ULL;

    float c[4][4][4];                  // [mt][nt][frag]
#pragma unroll
    for (int mt = 0; mt < 4; mt++)
#pragma unroll
        for (int nt = 0; nt < 4; nt++)
#pragma unroll
            for (int q = 0; q < 4; q++) c[mt][nt][q] = 0.f;

    // ---- stage loader (cp.async) ----
    auto load_stage = [&](int ch, int s) {
        float* As = sm + s * STAGE_FLOATS;
        float* Bs = As + AS_FLOATS;
        const int k0 = ch * KT;
#pragma unroll
        for (int i = 0; i < 4; i++) {              // A: 1024 float4 tasks
            int id = tid + i * 256;
            int m = id >> 3, kc = id & 7;
            uint32_t dst = smem_u32(As + m * AS_STRIDE + kc * 4);
            const float* src = x + (size_t)(rowBase + m) * DIM + k0 + kc * 4;
            CP_ASYNC16(dst, src);
        }
#pragma unroll
        for (int i = 0; i < 4; i++) {              // B: 1024 float4 tasks
            int id = tid + i * 256;
            int k = id >> 5, nc = id & 31;
            uint32_t dst = smem_u32(Bs + k * BS_STRIDE + nc * 4);
            const float* src = w + (size_t)(k0 + k) * NOUT + colBase + nc * 4;
            CP_ASYNC16(dst, src);
        }
        CP_COMMIT();
    };

    load_stage(0, 0);

    const int aBase = (wm * 64 + g) * AS_STRIDE + t;   // + mt*16*stride + s8 (+288 for +8 rows)
    const int bBase = t * BS_STRIDE + wn * 32 + g;     // + nt*8 + s8*stride (+544 for +4 k)

    for (int ch = 0; ch < NCHUNK; ch++) {
        const int s = ch & 1;
        if (ch + 1 < NCHUNK) { load_stage(ch + 1, (ch + 1) & 1); CP_WAIT(1); }
        else CP_WAIT(0);
        __syncthreads();

        const float* As = sm + s * STAGE_FLOATS;
        const float* Bs = As + AS_FLOATS;
#pragma unroll
        for (int s8 = 0; s8 < KT; s8 += 8) {
            uint32_t bf[4][2];
#pragma unroll
            for (int nt = 0; nt < 4; nt++) {
                const float* bp = Bs + bBase + nt * 8 + s8 * BS_STRIDE;
                bf[nt][0] = __float_as_uint(bp[0]);
                bf[nt][1] = __float_as_uint(bp[4 * BS_STRIDE]);
            }
#pragma unroll
            for (int mt = 0; mt < 4; mt++) {
                const float* ap = As + aBase + mt * (16 * AS_STRIDE) + s8;
                uint32_t a0 = __float_as_uint(ap[0]);
                uint32_t a1 = __float_as_uint(ap[8 * AS_STRIDE]);
                uint32_t a2 = __float_as_uint(ap[4]);
                uint32_t a3 = __float_as_uint(ap[8 * AS_STRIDE + 4]);
#pragma unroll
                for (int nt = 0; nt < 4; nt++)
                    MMA_TF32(c[mt][nt][0], c[mt][nt][1], c[mt][nt][2], c[mt][nt][3],
                             a0, a1, a2, a3, bf[nt][0], bf[nt][1]);
            }
        }
        __syncthreads();
    }

    // ---- epilogue: distances + stores + per-row argmin ----
#pragma unroll
    for (int mt = 0; mt < 4; mt++) {
        const int lrow0 = wm * 64 + mt * 16 + g;
        const int row0 = rowBase + lrow0;
        const int row1 = row0 + 8;
        const float xs0 = g_x2[row0];
        const float xs1 = g_x2[row1];
        unsigned long long b0 = ~0ULL, b1 = ~0ULL;
#pragma unroll
        for (int nt = 0; nt < 4; nt++) {
            const int col = colBase + wn * 32 + nt * 8 + t * 2;
            const float w20 = __ldg(&g_w2[col]);
            const float w21 = __ldg(&g_w2[col + 1]);
            float d00 = fmaxf(fmaf(-2.f, c[mt][nt][0], xs0 + w20), 0.f);
            float d01 = fmaxf(fmaf(-2.f, c[mt][nt][1], xs0 + w21), 0.f);
            float d10 = fmaxf(fmaf(-2.f, c[mt][nt][2], xs1 + w20), 0.f);
            float d11 = fmaxf(fmaf(-2.f, c[mt][nt][3], xs1 + w21), 0.f);
            unsigned long long p;
            p = ((unsigned long long)__float_as_uint(d00) << 32) | (unsigned)col;
            b0 = (p < b0) ? p : b0;
            p = ((unsigned long long)__float_as_uint(d01) << 32) | (unsigned)(col + 1);
            b0 = (p < b0) ? p : b0;
            p = ((unsigned long long)__float_as_uint(d10) << 32) | (unsigned)col;
            b1 = (p < b1) ? p : b1;
            p = ((unsigned long long)__float_as_uint(d11) << 32) | (unsigned)(col + 1);
            b1 = (p < b1) ? p : b1;
            *(float2*)&out[(size_t)row0 * NOUT + col] = make_float2(d00, d01);
            *(float2*)&out[(size_t)row1 * NOUT + col] = make_float2(d10, d11);
        }
        // reduce across the 4 lanes (t) of each quad sharing this row pair
#pragma unroll
        for (int m = 1; m < 4; m <<= 1) {
            unsigned long long q;
            q = __shfl_xor_sync(0xFFFFFFFFu, b0, m); b0 = (q < b0) ? q : b0;
            q = __shfl_xor_sync(0xFFFFFFFFu, b1, m); b1 = (q < b1) ? q : b1;
        }
        if (t == 0) {
            atomicMin(&sred[lrow0], b0);
            atomicMin(&sred[lrow0 + 8], b1);
        }
    }
    __syncthreads();
    if (tid < BM) atomicMin(&g_argmin[rowBase + tid], sred[tid]);
}

// ---------------------------------------------------------------------------
// phi kernel: cache row in smem, EXACT fp32 recheck of near-min candidates
// (covers tf32 error), separable Gaussian phi, multiply, store.
// ---------------------------------------------------------------------------
#define PHI_SMEM ((NOUT + 2 * SIDE) * 4)

__global__ __launch_bounds__(256)
void phi_kernel(float* __restrict__ out, const float* __restrict__ x,
                const float* __restrict__ w, const float* __restrict__ std_ptr) {
    extern __shared__ float srow[];                    // [NOUT] + er[128] + ec[128]
    float* er = srow + NOUT;
    float* ec = er + SIDE;
    __shared__ int s_cnt;
    __shared__ unsigned long long s_best;
    __shared__ int s_cands[64];
    __shared__ float s_inv;

    const int b = blockIdx.x, tid = threadIdx.x;
    const float4* src4 = (const float4*)(out + (size_t)b * NOUT);
    float4* row4 = (float4*)srow;
    for (int i = tid; i < NOUT / 4; i += 256) row4[i] = src4[i];
    if (tid == 0) { s_cnt = 0; s_best = ~0ULL; }
    __syncthreads();

    // collect candidates within margin of the (tf32) min
    const float minv = __uint_as_float((unsigned)(g_argmin[b] >> 32));
    const float thresh = minv + 1.0f;
    for (int n = tid; n < NOUT; n += 256) {
        if (srow[n] < thresh) {
            int p = atomicAdd(&s_cnt, 1);
            if (p < 64) s_cands[p] = n;
        }
    }
    __syncthreads();

    // exact fp32 recompute per candidate (one warp per candidate)
    const int ncand = min(s_cnt, 64);
    const int wid = tid >> 5, lid = tid & 31;
    const float* xr = x + (size_t)b * DIM;
    for (int j = wid; j < ncand; j += 8) {
        int col = s_cands[j];
        float acc = 0.f;
#pragma unroll
        for (int i = 0; i < 16; i++) {
            int k = i * 32 + lid;
            acc = fmaf(xr[k], w[(size_t)k * NOUT + col], acc);
        }
#pragma unroll
        for (int o = 16; o > 0; o >>= 1) acc += __shfl_down_sync(0xFFFFFFFFu, acc, o);
        if (lid == 0) {
            float d = fmaxf(g_x2[b] + g_w2[col] - 2.f * acc, 0.f);
            unsigned long long pk =
                ((unsigned long long)__float_as_uint(d) << 32) | (unsigned)col;
            atomicMin(&s_best, pk);
        }
    }
    __syncthreads();

    const int idx = (int)(s_best & 0xFFFFFFFFu);
    const int cr = idx >> 7, cc = idx & 127;
    const float stdv = *std_ptr;
    const float coef = 0.5f / (stdv * stdv);
    if (tid < SIDE) {
        float d = (float)(tid - cr);
        er[tid] = expf(-d * d * coef);
    } else if (tid < 2 * SIDE) {
        int tt = tid - SIDE;
        float d = (float)(tt - cc);
        ec[tt] = expf(-d * d * coef);
    }
    __syncthreads();
    if (tid == 0) {
        float sr = 0.f, sc = 0.f;
        for (int tt = 0; tt < SIDE; tt++) { sr += er[tt]; sc += ec[tt]; }
        s_inv = 1.0f / (sr * sc);
    }
    __syncthreads();

    const float inv = s_inv;
    float4* o4 = (float4*)(out + (size_t)b * NOUT);
    for (int i = tid; i < NOUT / 4; i += 256) {
        int n = i * 4;
        float fr = er[n >> 7] * inv;
        int c0 = n & 127;
        float4 v = row4[i];
        v.x *= fr * ec[c0 + 0];
        v.y *= fr * ec[c0 + 1];
        v.z *= fr * ec[c0 + 2];
        v.w *= fr * ec[c0 + 3];
        o4[i] = v;
    }
}

// ---------------------------------------------------------------------------
extern "C" void kernel_launch(void* const* d_in, const int* in_sizes, int n_in,
                              void* d_out, int out_size) {
    const float* x    = (const float*)d_in[0];   // (2048, 512)
    const float* wts  = (const float*)d_in[1];   // (512, 16384)
    const float* stdp = (const float*)d_in[2];   // scalar
    float* out = (float*)d_out;                  // (2048, 16384)

    cudaFuncSetAttribute(gemm_mma_kernel,
                         cudaFuncAttributeMaxDynamicSharedMemorySize, GEMM_SMEM);
    cudaFuncSetAttribute(phi_kernel,
                         cudaFuncAttributeMaxDynamicSharedMemorySize, PHI_SMEM);

    prep_w2_kernel<<<NOUT / 256, 256>>>(wts);
    prep_x2_kernel<<<BATCH / 8, 256>>>(x);

    dim3 grid(NOUT / BN, BATCH / BM);            // (128, 16)
    gemm_mma_kernel<<<grid, 256, GEMM_SMEM>>>(x, wts, out);

    phi_kernel<<<BATCH, 256, PHI_SMEM>>>(out, x, wts, stdp);
}

// round 13
// speedup vs baseline: 2.3810x; 1.0665x over previous
#include <cuda_runtime.h>
#include <cstdint>

#define BATCH 2048
#define DIM   512
#define NOUT  16384
#define SIDE  128

// ---------------- device scratch (no cudaMalloc allowed) ----------------
__device__ float g_w2[NOUT];
__device__ float g_x2[BATCH];
__device__ unsigned long long g_argmin[BATCH];

__device__ __forceinline__ uint32_t smem_u32(const void* p) {
    uint32_t a;
    asm("{ .reg .u64 t; cvta.to.shared.u64 t, %1; cvt.u32.u64 %0, t; }"
        : "=r"(a) : "l"(p));
    return a;
}

// ---------------------------------------------------------------------------
// Kernel: w2[n] = sum_d W[d][n]^2 (exact fp32)
// ---------------------------------------------------------------------------
__global__ void prep_w2_kernel(const float* __restrict__ w) {
    int n = blockIdx.x * blockDim.x + threadIdx.x;
    float s0 = 0.f, s1 = 0.f, s2 = 0.f, s3 = 0.f;
#pragma unroll 4
    for (int d = 0; d < DIM; d += 4) {
        float a = w[(size_t)(d + 0) * NOUT + n];
        float b = w[(size_t)(d + 1) * NOUT + n];
        float c = w[(size_t)(d + 2) * NOUT + n];
        float e = w[(size_t)(d + 3) * NOUT + n];
        s0 = fmaf(a, a, s0); s1 = fmaf(b, b, s1);
        s2 = fmaf(c, c, s2); s3 = fmaf(e, e, s3);
    }
    g_w2[n] = (s0 + s1) + (s2 + s3);
}

// ---------------------------------------------------------------------------
// Kernel: x2[b] = sum_d x[b][d]^2 (exact) + init argmin. One warp per row.
// ---------------------------------------------------------------------------
__global__ void prep_x2_kernel(const float* __restrict__ x) {
    int warp = (blockIdx.x * blockDim.x + threadIdx.x) >> 5;
    int lane = threadIdx.x & 31;
    if (warp >= BATCH) return;
    const float4* row = (const float4*)(x + (size_t)warp * DIM);
    float s = 0.f;
#pragma unroll
    for (int i = 0; i < 4; i++) {
        float4 v = row[lane + i * 32];
        s = fmaf(v.x, v.x, s); s = fmaf(v.y, v.y, s);
        s = fmaf(v.z, v.z, s); s = fmaf(v.w, v.w, s);
    }
#pragma unroll
    for (int off = 16; off > 0; off >>= 1) s += __shfl_down_sync(0xFFFFFFFFu, s, off);
    if (lane == 0) { g_x2[warp] = s; g_argmin[warp] = ~0ULL; }
}

// ---------------------------------------------------------------------------
// tf32 mma.sync GEMM. Tile: 128(M) x 128(N), BK=32, 4 warps in 2x2 grid,
// warp tile 64x64 (LDS/MMA ratio 1.0 vs 1.5 for 64x32).
// Double-buffered cp.async. Epilogue: dist = max(x2+w2-2dot,0), per-row
// argmin (quad shfl -> smem atomic -> global atomic), direct float2 stores.
// ---------------------------------------------------------------------------
#define BM 128
#define BN 128
#define KT 32
#define NCHUNK (DIM / KT)              // 16
#define AS_STRIDE 36                   // floats; banks 4g+t conflict-free
#define BS_STRIDE 136                  // floats; banks 8t+g conflict-free
#define AS_FLOATS (BM * AS_STRIDE)     // 4608
#define BS_FLOATS (KT * BS_STRIDE)     // 4352
#define STAGE_FLOATS (AS_FLOATS + BS_FLOATS)   // 8960
#define GEMM_SMEM (2 * STAGE_FLOATS * 4 + 1024) // 72704 bytes

#define CP_ASYNC16(dst, src) \
    asm volatile("cp.async.cg.shared.global [%0], [%1], 16;" :: "r"(dst), "l"(src))
#define CP_COMMIT() asm volatile("cp.async.commit_group;" ::: "memory")
#define CP_WAIT(n)  asm volatile("cp.async.wait_group %0;" :: "n"(n) : "memory")

#define MMA_TF32(c0, c1, c2, c3, a0, a1, a2, a3, b0, b1) \
    asm volatile( \
        "mma.sync.aligned.m16n8k8.row.col.f32.tf32.tf32.f32 " \
        "{%0,%1,%2,%3}, {%4,%5,%6,%7}, {%8,%9}, {%0,%1,%2,%3};" \
        : "+f"(c0), "+f"(c1), "+f"(c2), "+f"(c3) \
        : "r"(a0), "r"(a1), "r"(a2), "r"(a3), "r"(b0), "r"(b1))

__global__ __launch_bounds__(128, 2)
void gemm_mma_kernel(const float* __restrict__ x, const float* __restrict__ w,
                     float* __restrict__ out) {
    extern __shared__ float sm[];
    unsigned long long* sred = (unsigned long long*)(sm + 2 * STAGE_FLOATS);

    const int tid = threadIdx.x;
    const int lane = tid & 31;
    const int wrp = tid >> 5;          // 0..3
    const int wm = wrp >> 1;           // 0..1  (M half)
    const int wn = wrp & 1;            // 0..1  (N half)
    const int g = lane >> 2;           // 0..7
    const int t = lane & 3;            // 0..3
    const int rowBase = blockIdx.y * BM;
    const int colBase = blockIdx.x * BN;

    if (tid < BM) sred[tid] = ~0ULL;

    float c[4][8][4];                  // [mt][nt][frag] = 128 accum regs
#pragma unroll
    for (int mt = 0; mt < 4; mt++)
#pragma unroll
        for (int nt = 0; nt < 8; nt++)
#pragma unroll
            for (int q = 0; q < 4; q++) c[mt][nt][q] = 0.f;

    // ---- stage loader (cp.async), 128 threads ----
    auto load_stage = [&](int ch, int s) {
        float* As = sm + s * STAGE_FLOATS;
        float* Bs = As + AS_FLOATS;
        const int k0 = ch * KT;
#pragma unroll
        for (int i = 0; i < 8; i++) {              // A: 1024 float4 tasks
            int id = tid + i * 128;
            int m = id >> 3, kc = id & 7;
            uint32_t dst = smem_u32(As + m * AS_STRIDE + kc * 4);
            const float* src = x + (size_t)(rowBase + m) * DIM + k0 + kc * 4;
            CP_ASYNC16(dst, src);
        }
#pragma unroll
        for (int i = 0; i < 8; i++) {              // B: 1024 float4 tasks
            int id = tid + i * 128;
            int k = id >> 5, nc = id & 31;
            uint32_t dst = smem_u32(Bs + k * BS_STRIDE + nc * 4);
            const float* src = w + (size_t)(k0 + k) * NOUT + colBase + nc * 4;
            CP_ASYNC16(dst, src);
        }
        CP_COMMIT();
    };

    load_stage(0, 0);

    const int aBase = (wm * 64 + g) * AS_STRIDE + t;
    const int bBase = t * BS_STRIDE + wn * 64 + g;

    for (int ch = 0; ch < NCHUNK; ch++) {
        const int s = ch & 1;
        if (ch + 1 < NCHUNK) { load_stage(ch + 1, (ch + 1) & 1); CP_WAIT(1); }
        else CP_WAIT(0);
        __syncthreads();

        const float* As = sm + s * STAGE_FLOATS;
        const float* Bs = As + AS_FLOATS;
#pragma unroll
        for (int s8 = 0; s8 < KT; s8 += 8) {
            uint32_t bf[8][2];
#pragma unroll
            for (int nt = 0; nt < 8; nt++) {
                const float* bp = Bs + bBase + nt * 8 + s8 * BS_STRIDE;
                bf[nt][0] = __float_as_uint(bp[0]);
                bf[nt][1] = __float_as_uint(bp[4 * BS_STRIDE]);
            }
#pragma unroll
            for (int mt = 0; mt < 4; mt++) {
                const float* ap = As + aBase + mt * (16 * AS_STRIDE) + s8;
                uint32_t a0 = __float_as_uint(ap[0]);
                uint32_t a1 = __float_as_uint(ap[8 * AS_STRIDE]);
                uint32_t a2 = __float_as_uint(ap[4]);
                uint32_t a3 = __float_as_uint(ap[8 * AS_STRIDE + 4]);
#pragma unroll
                for (int nt = 0; nt < 8; nt++)
                    MMA_TF32(c[mt][nt][0], c[mt][nt][1], c[mt][nt][2], c[mt][nt][3],
                             a0, a1, a2, a3, bf[nt][0], bf[nt][1]);
            }
        }
        __syncthreads();
    }

    // ---- epilogue: distances + stores + per-row argmin ----
#pragma unroll
    for (int mt = 0; mt < 4; mt++) {
        const int lrow0 = wm * 64 + mt * 16 + g;
        const int row0 = rowBase + lrow0;
        const int row1 = row0 + 8;
        const float xs0 = g_x2[row0];
        const float xs1 = g_x2[row1];
        unsigned long long b0 = ~0ULL, b1 = ~0ULL;
#pragma unroll
        for (int nt = 0; nt < 8; nt++) {
            const int col = colBase + wn * 64 + nt * 8 + t * 2;
            const float w20 = __ldg(&g_w2[col]);
            const float w21 = __ldg(&g_w2[col + 1]);
            float d00 = fmaxf(fmaf(-2.f, c[mt][nt][0], xs0 + w20), 0.f);
            float d01 = fmaxf(fmaf(-2.f, c[mt][nt][1], xs0 + w21), 0.f);
            float d10 = fmaxf(fmaf(-2.f, c[mt][nt][2], xs1 + w20), 0.f);
            float d11 = fmaxf(fmaf(-2.f, c[mt][nt][3], xs1 + w21), 0.f);
            unsigned long long p;
            p = ((unsigned long long)__float_as_uint(d00) << 32) | (unsigned)col;
            b0 = (p < b0) ? p : b0;
            p = ((unsigned long long)__float_as_uint(d01) << 32) | (unsigned)(col + 1);
            b0 = (p < b0) ? p : b0;
            p = ((unsigned long long)__float_as_uint(d10) << 32) | (unsigned)col;
            b1 = (p < b1) ? p : b1;
            p = ((unsigned long long)__float_as_uint(d11) << 32) | (unsigned)(col + 1);
            b1 = (p < b1) ? p : b1;
            *(float2*)&out[(size_t)row0 * NOUT + col] = make_float2(d00, d01);
            *(float2*)&out[(size_t)row1 * NOUT + col] = make_float2(d10, d11);
        }
        // reduce across the 4 lanes (t) of each quad sharing this row pair
#pragma unroll
        for (int m = 1; m < 4; m <<= 1) {
            unsigned long long q;
            q = __shfl_xor_sync(0xFFFFFFFFu, b0, m); b0 = (q < b0) ? q : b0;
            q = __shfl_xor_sync(0xFFFFFFFFu, b1, m); b1 = (q < b1) ? q : b1;
        }
        if (t == 0) {
            atomicMin(&sred[lrow0], b0);
            atomicMin(&sred[lrow0 + 8], b1);
        }
    }
    __syncthreads();
    if (tid < BM) atomicMin(&g_argmin[rowBase + tid], sred[tid]);
}

// ---------------------------------------------------------------------------
// phi kernel (streaming, no row cache -> full occupancy):
//   pass 1: stream row from global, collect candidates < tf32_min + 1.0
//   exact fp32 recheck of candidates (fixes tf32 argmin flips)
//   pass 2: stream row again (L2-hot), multiply by separable phi, store.
// ---------------------------------------------------------------------------
__global__ __launch_bounds__(256)
void phi_kernel(float* __restrict__ out, const float* __restrict__ x,
                const float* __restrict__ w, const float* __restrict__ std_ptr) {
    __shared__ float er[SIDE], ec[SIDE];
    __shared__ int s_cnt;
    __shared__ unsigned long long s_best;
    __shared__ int s_cands[64];

    const int b = blockIdx.x, tid = threadIdx.x;
    float4* row4 = (float4*)(out + (size_t)b * NOUT);

    if (tid == 0) { s_cnt = 0; s_best = ~0ULL; }
    __syncthreads();

    // pass 1: collect candidates within margin of the (tf32) min
    const float minv = __uint_as_float((unsigned)(g_argmin[b] >> 32));
    const float thresh = minv + 1.0f;
    for (int i = tid; i < NOUT / 4; i += 256) {
        float4 v = row4[i];
        int n = i * 4;
        if (v.x < thresh) { int p = atomicAdd(&s_cnt, 1); if (p < 64) s_cands[p] = n; }
        if (v.y < thresh) { int p = atomicAdd(&s_cnt, 1); if (p < 64) s_cands[p] = n + 1; }
        if (v.z < thresh) { int p = atomicAdd(&s_cnt, 1); if (p < 64) s_cands[p] = n + 2; }
        if (v.w < thresh) { int p = atomicAdd(&s_cnt, 1); if (p < 64) s_cands[p] = n + 3; }
    }
    __syncthreads();

    // exact fp32 recompute per candidate (one warp per candidate)
    const int ncand = min(s_cnt, 64);
    const int wid = tid >> 5, lid = tid & 31;
    const float* xr = x + (size_t)b * DIM;
    for (int j = wid; j < ncand; j += 8) {
        int col = s_cands[j];
        float acc = 0.f;
#pragma unroll
        for (int i = 0; i < 16; i++) {
            int k = i * 32 + lid;
            acc = fmaf(xr[k], w[(size_t)k * NOUT + col], acc);
        }
#pragma unroll
        for (int o = 16; o > 0; o >>= 1) acc += __shfl_down_sync(0xFFFFFFFFu, acc, o);
        if (lid == 0) {
            float d = fmaxf(g_x2[b] + g_w2[col] - 2.f * acc, 0.f);
            unsigned long long pk =
                ((unsigned long long)__float_as_uint(d) << 32) | (unsigned)col;
            atomicMin(&s_best, pk);
        }
    }
    __syncthreads();

    // separable Gaussian tables
    const int idx = (int)(s_best & 0xFFFFFFFFu);
    const int cr = idx >> 7, cc = idx & 127;
    const float stdv = *std_ptr;
    const float coef = 0.5f / (stdv * stdv);
    if (tid < SIDE) {
        float d = (float)(tid - cr);
        er[tid] = expf(-d * d * coef);
    } else if (tid < 2 * SIDE) {
        int tt = tid - SIDE;
        float d = (float)(tt - cc);
        ec[tt] = expf(-d * d * coef);
    }
    __syncthreads();
    if (tid == 0) {
        float sr = 0.f, sc = 0.f;
        for (int tt = 0; tt < SIDE; tt++) { sr += er[tt]; sc += ec[tt]; }
        float inv = 1.0f / (sr * sc);
        for (int tt = 0; tt < SIDE; tt++) er[tt] *= inv;   // fold inv into er
    }
    __syncthreads();

    // pass 2: multiply + store
    for (int i = tid; i < NOUT / 4; i += 256) {
        int n = i * 4;
        float fr = er[n >> 7];
        int c0 = n & 127;
        float4 v = row4[i];
        v.x *= fr * ec[c0 + 0];
        v.y *= fr * ec[c0 + 1];
        v.z *= fr * ec[c0 + 2];
        v.w *= fr * ec[c0 + 3];
        row4[i] = v;
    }
}

// ---------------------------------------------------------------------------
extern "C" void kernel_launch(void* const* d_in, const int* in_sizes, int n_in,
                              void* d_out, int out_size) {
    const float* x    = (const float*)d_in[0];   // (2048, 512)
    const float* wts  = (const float*)d_in[1];   // (512, 16384)
    const float* stdp = (const float*)d_in[2];   // scalar
    float* out = (float*)d_out;                  // (2048, 16384)

    cudaFuncSetAttribute(gemm_mma_kernel,
                         cudaFuncAttributeMaxDynamicSharedMemorySize, GEMM_SMEM);

    prep_w2_kernel<<<NOUT / 256, 256>>>(wts);
    prep_x2_kernel<<<BATCH / 8, 256>>>(x);

    dim3 grid(NOUT / BN, BATCH / BM);            // (128, 16)
    gemm_mma_kernel<<<grid, 128, GEMM_SMEM>>>(x, wts, out);

    phi_kernel<<<BATCH, 256>>>(out, x, wts, stdp);
}

// round 14
// speedup vs baseline: 3.4537x; 1.4505x over previous
#include <cuda_runtime.h>
#include <cuda_fp16.h>
#include <cstdint>

#define BATCH 2048
#define DIM   512
#define NOUT  16384
#define SIDE  128

#define BM 128
#define BN 128
#define GRIDX (NOUT / BN)              // 128 column tiles

// ---------------- device scratch (no cudaMalloc allowed) ----------------
__device__ float g_w2[NOUT];
__device__ float g_x2[BATCH];
__device__ unsigned long long g_tilemin[(size_t)BATCH * GRIDX];  // 2MB
__device__ uint32_t g_xh[(size_t)BATCH * DIM / 2];               // fp16 pairs [b][k], 2MB
__device__ uint32_t g_wth[(size_t)NOUT * DIM / 2];               // fp16 pairs [n][k], 16MB

__device__ __forceinline__ uint32_t smem_u32(const void* p) {
    uint32_t a;
    asm("{ .reg .u64 t; cvta.to.shared.u64 t, %1; cvt.u32.u64 %0, t; }"
        : "=r"(a) : "l"(p));
    return a;
}

__device__ __forceinline__ uint32_t packh2(float lo, float hi) {
    __half2 h = __floats2half2_rn(lo, hi);      // .x = lo (low 16 bits)
    return *(uint32_t*)&h;
}

// ---------------------------------------------------------------------------
// w2[n] = sum_d W[d][n]^2 (exact fp32)
// ---------------------------------------------------------------------------
__global__ void prep_w2_kernel(const float* __restrict__ w) {
    int n = blockIdx.x * blockDim.x + threadIdx.x;
    float s0 = 0.f, s1 = 0.f, s2 = 0.f, s3 = 0.f;
#pragma unroll 4
    for (int d = 0; d < DIM; d += 4) {
        float a = w[(size_t)(d + 0) * NOUT + n];
        float b = w[(size_t)(d + 1) * NOUT + n];
        float c = w[(size_t)(d + 2) * NOUT + n];
        float e = w[(size_t)(d + 3) * NOUT + n];
        s0 = fmaf(a, a, s0); s1 = fmaf(b, b, s1);
        s2 = fmaf(c, c, s2); s3 = fmaf(e, e, s3);
    }
    g_w2[n] = (s0 + s1) + (s2 + s3);
}

// ---------------------------------------------------------------------------
// x2[b] = sum_d x[b][d]^2 (exact) + fp16 conversion of x. One warp per row.
// ---------------------------------------------------------------------------
__global__ void prep_x2_kernel(const float* __restrict__ x) {
    int warp = (blockIdx.x * blockDim.x + threadIdx.x) >> 5;
    int lane = threadIdx.x & 31;
    if (warp >= BATCH) return;
    const float4* row = (const float4*)(x + (size_t)warp * DIM);
    uint2* xh2 = (uint2*)(g_xh + (size_t)warp * (DIM / 2));
    float s = 0.f;
#pragma unroll
    for (int i = 0; i < 4; i++) {
        float4 v = row[lane + i * 32];
        s = fmaf(v.x, v.x, s); s = fmaf(v.y, v.y, s);
        s = fmaf(v.z, v.z, s); s = fmaf(v.w, v.w, s);
        xh2[lane + i * 32] = make_uint2(packh2(v.x, v.y), packh2(v.z, v.w));
    }
#pragma unroll
    for (int off = 16; off > 0; off >>= 1) s += __shfl_down_sync(0xFFFFFFFFu, s, off);
    if (lane == 0) g_x2[warp] = s;
}

// ---------------------------------------------------------------------------
// Convert + transpose W[k][n] fp32 -> g_wth[n][k] fp16 pairs. 32x32 tiles.
// ---------------------------------------------------------------------------
__global__ void convert_w_kernel(const float* __restrict__ w) {
    __shared__ float t[32][33];
    const int nb = blockIdx.x * 32, kb = blockIdx.y * 32;
    const int tid = threadIdx.x;
#pragma unroll
    for (int i = 0; i < 4; i++) {
        int id = tid + i * 256;
        int kk = id >> 5, nn = id & 31;
        t[kk][nn] = w[(size_t)(kb + kk) * NOUT + nb + nn];
    }
    __syncthreads();
#pragma unroll
    for (int i = 0; i < 2; i++) {
        int id = tid + i * 256;
        int nl = id >> 4, kl = id & 15;
        g_wth[(size_t)(nb + nl) * (DIM / 2) + (kb >> 1) + kl] =
            packh2(t[2 * kl][nl], t[2 * kl + 1][nl]);
    }
}

// ---------------------------------------------------------------------------
// fp16 mma.sync GEMM (m16n8k16: 2x MACs/instr vs tf32 k8 at same issue cost;
// same 10-bit mantissa as tf32 -> same precision).
// Tile: 128x128, KT=64 (32 pairs), 4 warps 2x2, warp tile 64x64.
// A and B both stored [row][k-pair] with stride 36 u32 (conflict-free).
// Epilogue: dist = max(x2+w2-2dot,0), per-row argmin -> g_tilemin.
// ---------------------------------------------------------------------------
#define KT 64
#define NCHUNK (DIM / KT)              // 8
#define RS 36                          // u32 stride per row (32 pairs + pad)
#define TILE_U32 (128 * RS)            // 4608 u32 per operand tile
#define STAGE_U32 (2 * TILE_U32)       // 9216
#define GEMM_SMEM (2 * STAGE_U32 * 4 + 1024)   // 74752 bytes

#define CP_ASYNC16(dst, src) \
    asm volatile("cp.async.cg.shared.global [%0], [%1], 16;" :: "r"(dst), "l"(src))
#define CP_COMMIT() asm volatile("cp.async.commit_group;" ::: "memory")
#define CP_WAIT(n)  asm volatile("cp.async.wait_group %0;" :: "n"(n) : "memory")

#define MMA_F16(c0, c1, c2, c3, a0, a1, a2, a3, b0, b1) \
    asm volatile( \
        "mma.sync.aligned.m16n8k16.row.col.f32.f16.f16.f32 " \
        "{%0,%1,%2,%3}, {%4,%5,%6,%7}, {%8,%9}, {%0,%1,%2,%3};" \
        : "+f"(c0), "+f"(c1), "+f"(c2), "+f"(c3) \
        : "r"(a0), "r"(a1), "r"(a2), "r"(a3), "r"(b0), "r"(b1))

__global__ __launch_bounds__(128, 2)
void gemm_mma_kernel(float* __restrict__ out) {
    extern __shared__ uint32_t smU[];
    unsigned long long* sred = (unsigned long long*)(smU + 2 * STAGE_U32);

    const int tid = threadIdx.x;
    const int lane = tid & 31;
    const int wrp = tid >> 5;          // 0..3
    const int wm = wrp >> 1;           // 0..1
    const int wn = wrp & 1;            // 0..1
    const int g = lane >> 2;           // 0..7
    const int t = lane & 3;            // 0..3
    const int rowBase = blockIdx.y * BM;
    const int colBase = blockIdx.x * BN;

    if (tid < BM) sred[tid] = ~0ULL;

    float c[4][8][4];
#pragma unroll
    for (int mt = 0; mt < 4; mt++)
#pragma unroll
        for (int nt = 0; nt < 8; nt++)
#pragma unroll
            for (int q = 0; q < 4; q++) c[mt][nt][q] = 0.f;

    auto load_stage = [&](int ch, int s) {
        uint32_t* As = smU + s * STAGE_U32;
        uint32_t* Bs = As + TILE_U32;
        const int p0 = ch * (KT / 2);                  // pair offset in [0,256)
#pragma unroll
        for (int i = 0; i < 8; i++) {                  // A: 1024 16B tasks
            int id = tid + i * 128;
            int m = id >> 3, kc = id & 7;
            uint32_t dst = smem_u32(As + m * RS + kc * 4);
            const uint32_t* src = g_xh + (size_t)(rowBase + m) * (DIM / 2) + p0 + kc * 4;
            CP_ASYNC16(dst, src);
        }
#pragma unroll
        for (int i = 0; i < 8; i++) {                  // B: 1024 16B tasks
            int id = tid + i * 128;
            int m = id >> 3, kc = id & 7;
            uint32_t dst = smem_u32(Bs + m * RS + kc * 4);
            const uint32_t* src = g_wth + (size_t)(colBase + m) * (DIM / 2) + p0 + kc * 4;
            CP_ASYNC16(dst, src);
        }
        CP_COMMIT();
    };

    load_stage(0, 0);

    const int aBase = (wm * 64 + g) * RS + t;
    const int bBase = (wn * 64 + g) * RS + t;

    for (int ch = 0; ch < NCHUNK; ch++) {
        const int s = ch & 1;
        if (ch + 1 < NCHUNK) { load_stage(ch + 1, (ch + 1) & 1); CP_WAIT(1); }
        else CP_WAIT(0);
        __syncthreads();

        const uint32_t* As = smU + s * STAGE_U32;
        const uint32_t* Bs = As + TILE_U32;
#pragma unroll
        for (int s16 = 0; s16 < 4; s16++) {            // 4 x K16 = 64
            const int kb = s16 * 8;                    // pair base
            uint32_t bf[8][2];
#pragma unroll
            for (int nt = 0; nt < 8; nt++) {
                const uint32_t* bp = Bs + bBase + nt * 8 * RS + kb;
                bf[nt][0] = bp[0];
                bf[nt][1] = bp[4];
            }
#pragma unroll
            for (int mt = 0; mt < 4; mt++) {
                const uint32_t* ap = As + aBase + mt * (16 * RS) + kb;
                uint32_t a0 = ap[0];
                uint32_t a1 = ap[8 * RS];
                uint32_t a2 = ap[4];
                uint32_t a3 = ap[8 * RS + 4];
#pragma unroll
                for (int nt = 0; nt < 8; nt++)
                    MMA_F16(c[mt][nt][0], c[mt][nt][1], c[mt][nt][2], c[mt][nt][3],
                            a0, a1, a2, a3, bf[nt][0], bf[nt][1]);
            }
        }
        __syncthreads();
    }

    // ---- epilogue: distances + stores + per-row argmin ----
#pragma unroll
    for (int mt = 0; mt < 4; mt++) {
        const int lrow0 = wm * 64 + mt * 16 + g;
        const int row0 = rowBase + lrow0;
        const int row1 = row0 + 8;
        const float xs0 = g_x2[row0];
        const float xs1 = g_x2[row1];
        unsigned long long b0 = ~0ULL, b1 = ~0ULL;
#pragma unroll
        for (int nt = 0; nt < 8; nt++) {
            const int col = colBase + wn * 64 + nt * 8 + t * 2;
            const float w20 = __ldg(&g_w2[col]);
            const float w21 = __ldg(&g_w2[col + 1]);
            float d00 = fmaxf(fmaf(-2.f, c[mt][nt][0], xs0 + w20), 0.f);
            float d01 = fmaxf(fmaf(-2.f, c[mt][nt][1], xs0 + w21), 0.f);
            float d10 = fmaxf(fmaf(-2.f, c[mt][nt][2], xs1 + w20), 0.f);
            float d11 = fmaxf(fmaf(-2.f, c[mt][nt][3], xs1 + w21), 0.f);
            unsigned long long p;
            p = ((unsigned long long)__float_as_uint(d00) << 32) | (unsigned)col;
            b0 = (p < b0) ? p : b0;
            p = ((unsigned long long)__float_as_uint(d01) << 32) | (unsigned)(col + 1);
            b0 = (p < b0) ? p : b0;
            p = ((unsigned long long)__float_as_uint(d10) << 32) | (unsigned)col;
            b1 = (p < b1) ? p : b1;
            p = ((unsigned long long)__float_as_uint(d11) << 32) | (unsigned)(col + 1);
            b1 = (p < b1) ? p : b1;
            *(float2*)&out[(size_t)row0 * NOUT + col] = make_float2(d00, d01);
            *(float2*)&out[(size_t)row1 * NOUT + col] = make_float2(d10, d11);
        }
#pragma unroll
        for (int m = 1; m < 4; m <<= 1) {
            unsigned long long q;
            q = __shfl_xor_sync(0xFFFFFFFFu, b0, m); b0 = (q < b0) ? q : b0;
            q = __shfl_xor_sync(0xFFFFFFFFu, b1, m); b1 = (q < b1) ? q : b1;
        }
        if (t == 0) {
            atomicMin(&sred[lrow0], b0);
            atomicMin(&sred[lrow0 + 8], b1);
        }
    }
    __syncthreads();
    if (tid < BM)
        g_tilemin[(size_t)(rowBase + tid) * GRIDX + blockIdx.x] = sred[tid];
}

// ---------------------------------------------------------------------------
// phi kernel: global min from 128 per-tile minima (no full-row scan pass),
// candidate tiles -> candidate cols -> EXACT fp32 recheck, separable phi.
// ---------------------------------------------------------------------------
__global__ __launch_bounds__(256)
void phi_kernel(float* __restrict__ out, const float* __restrict__ x,
                const float* __restrict__ w, const float* __restrict__ std_ptr) {
    __shared__ float er[SIDE], ec[SIDE];
    __shared__ unsigned long long s_min0, s_best;
    __shared__ int s_tcnt, s_cnt, s_over;
    __shared__ int s_tiles[16], s_cands[64];

    const int b = blockIdx.x, tid = threadIdx.x;
    if (tid == 0) { s_min0 = ~0ULL; s_best = ~0ULL; s_tcnt = 0; s_cnt = 0; s_over = 0; }
    __syncthreads();

    unsigned long long tm = ~0ULL;
    if (tid < GRIDX) {
        tm = g_tilemin[(size_t)b * GRIDX + tid];
        atomicMin(&s_min0, tm);
    }
    __syncthreads();

    const float minv = __uint_as_float((unsigned)(s_min0 >> 32));
    const float thresh = minv + 1.0f;
    if (tid < GRIDX && __uint_as_float((unsigned)(tm >> 32)) < thresh) {
        int p = atomicAdd(&s_tcnt, 1);
        if (p < 16) s_tiles[p] = tid; else s_over = 1;
    }
    __syncthreads();

    const float* rowp = out + (size_t)b * NOUT;
    if (!s_over) {
        const int ntile = min(s_tcnt, 16);
        for (int j = 0; j < ntile; j++) {
            if (tid < BN) {
                int n = s_tiles[j] * BN + tid;
                if (rowp[n] < thresh) {
                    int p = atomicAdd(&s_cnt, 1);
                    if (p < 64) s_cands[p] = n;
                }
            }
        }
    } else {
        for (int n = tid; n < NOUT; n += 256) {
            if (rowp[n] < thresh) {
                int p = atomicAdd(&s_cnt, 1);
                if (p < 64) s_cands[p] = n;
            }
        }
    }
    __syncthreads();

    // exact fp32 recompute per candidate (one warp per candidate)
    const int ncand = min(s_cnt, 64);
    const int wid = tid >> 5, lid = tid & 31;
    const float* xr = x + (size_t)b * DIM;
    for (int j = wid; j < ncand; j += 8) {
        int col = s_cands[j];
        float acc = 0.f;
#pragma unroll
        for (int i = 0; i < 16; i++) {
            int k = i * 32 + lid;
            acc = fmaf(xr[k], w[(size_t)k * NOUT + col], acc);
        }
#pragma unroll
        for (int o = 16; o > 0; o >>= 1) acc += __shfl_down_sync(0xFFFFFFFFu, acc, o);
        if (lid == 0) {
            float d = fmaxf(g_x2[b] + g_w2[col] - 2.f * acc, 0.f);
            unsigned long long pk =
                ((unsigned long long)__float_as_uint(d) << 32) | (unsigned)col;
            atomicMin(&s_best, pk);
        }
    }
    __syncthreads();

    // separable Gaussian tables
    const int idx = (int)(s_best & 0xFFFFFFFFu);
    const int cr = idx >> 7, cc = idx & 127;
    const float stdv = *std_ptr;
    const float coef = 0.5f / (stdv * stdv);
    if (tid < SIDE) {
        float d = (float)(tid - cr);
        er[tid] = expf(-d * d * coef);
    } else if (tid < 2 * SIDE) {
        int tt = tid - SIDE;
        float d = (float)(tt - cc);
        ec[tt] = expf(-d * d * coef);
    }
    __syncthreads();
    if (tid == 0) {
        float sr = 0.f, sc = 0.f;
        for (int tt = 0; tt < SIDE; tt++) { sr += er[tt]; sc += ec[tt]; }
        float inv = 1.0f / (sr * sc);
        for (int tt = 0; tt < SIDE; tt++) er[tt] *= inv;   // fold inv into er
    }
    __syncthreads();

    float4* row4 = (float4*)(out + (size_t)b * NOUT);
    for (int i = tid; i < NOUT / 4; i += 256) {
        int n = i * 4;
        float fr = er[n >> 7];
        int c0 = n & 127;
        float4 v = row4[i];
        v.x *= fr * ec[c0 + 0];
        v.y *= fr * ec[c0 + 1];
        v.z *= fr * ec[c0 + 2];
        v.w *= fr * ec[c0 + 3];
        row4[i] = v;
    }
}

// ---------------------------------------------------------------------------
extern "C" void kernel_launch(void* const* d_in, const int* in_sizes, int n_in,
                              void* d_out, int out_size) {
    const float* x    = (const float*)d_in[0];   // (2048, 512)
    const float* wts  = (const float*)d_in[1];   // (512, 16384)
    const float* stdp = (const float*)d_in[2];   // scalar
    float* out = (float*)d_out;                  // (2048, 16384)

    cudaFuncSetAttribute(gemm_mma_kernel,
                         cudaFuncAttributeMaxDynamicSharedMemorySize, GEMM_SMEM);

    prep_w2_kernel<<<NOUT / 256, 256>>>(wts);
    prep_x2_kernel<<<BATCH / 8, 256>>>(x);
    convert_w_kernel<<<dim3(NOUT / 32, DIM / 32), 256>>>(wts);

    dim3 grid(NOUT / BN, BATCH / BM);            // (128, 16)
    gemm_mma_kernel<<<grid, 128, GEMM_SMEM>>>(out);

    phi_kernel<<<BATCH, 256>>>(out, x, wts, stdp);
}